// round 7
// baseline (speedup 1.0000x reference)
#include <cuda_runtime.h>
#include <cuda_fp16.h>
#include <cstdint>
#include <math.h>

// Problem constants
#define D_MODEL 4096
#define TWO_D   8192
#define NB      8
#define SEQ     512
#define LAMBDA_INIT 0.8f

// ---------------------------------------------------------------------------
// Scratch (static device globals; no runtime allocation allowed)
// ---------------------------------------------------------------------------
__device__ __align__(256) __half g_xh [(size_t)4096 * 4096];
__device__ __align__(256) __half g_wqh[(size_t)TWO_D * 4096];
__device__ __align__(256) __half g_wql[(size_t)TWO_D * 4096];
__device__ __align__(256) __half g_wkh[(size_t)TWO_D * 4096];
__device__ __align__(256) __half g_wkl[(size_t)TWO_D * 4096];
__device__ __align__(256) __half g_wvh[(size_t)TWO_D * 4096];
__device__ __align__(256) __half g_wvl[(size_t)TWO_D * 4096];
__device__ __align__(256) __half g_qh [(size_t)NB * SEQ * TWO_D];
__device__ __align__(256) __half g_ql [(size_t)NB * SEQ * TWO_D];
__device__ __align__(256) __half g_kh [(size_t)NB * SEQ * TWO_D];
__device__ __align__(256) __half g_kl [(size_t)NB * SEQ * TWO_D];
__device__ __align__(256) float  g_v  [(size_t)NB * SEQ * TWO_D];
__device__ __align__(256) __half g_vth[(size_t)NB * TWO_D * SEQ];
__device__ __align__(256) __half g_vtl[(size_t)NB * TWO_D * SEQ];
__device__ __align__(256) float  g_l1 [(size_t)NB * SEQ * SEQ];
__device__ __align__(256) float  g_l2 [(size_t)NB * SEQ * SEQ];
__device__ __align__(256) __half g_sch[(size_t)NB * SEQ * SEQ];
__device__ __align__(256) __half g_scl[(size_t)NB * SEQ * SEQ];

// ---------------------------------------------------------------------------
// PTX primitives (arch-neutral: sm_80+)
// ---------------------------------------------------------------------------
__device__ __forceinline__ uint32_t smem_u32(const void* p) {
    uint32_t a;
    asm("{ .reg .u64 t; cvta.to.shared.u64 t, %1; cvt.u32.u64 %0, t; }"
        : "=r"(a) : "l"(p));
    return a;
}

__device__ __forceinline__ void cpa16(uint32_t dst, const void* src) {
    asm volatile("cp.async.cg.shared.global [%0], [%1], 16;\n"
                 :: "r"(dst), "l"(src));
}
#define CP_COMMIT() asm volatile("cp.async.commit_group;\n" ::: "memory")
#define CP_WAIT(N)  asm volatile("cp.async.wait_group %0;\n" :: "n"(N) : "memory")

#define LDSM4(R, addr) \
    asm volatile("ldmatrix.sync.aligned.m8n8.x4.shared.b16 {%0,%1,%2,%3}, [%4];" \
        : "=r"((R)[0]), "=r"((R)[1]), "=r"((R)[2]), "=r"((R)[3]) : "r"(addr))

__device__ __forceinline__ void mma_f16(float* c, const uint32_t* a,
                                        uint32_t b0, uint32_t b1) {
    asm volatile(
        "mma.sync.aligned.m16n8k16.row.col.f32.f16.f16.f32 "
        "{%0,%1,%2,%3}, {%4,%5,%6,%7}, {%8,%9}, {%0,%1,%2,%3};"
        : "+f"(c[0]), "+f"(c[1]), "+f"(c[2]), "+f"(c[3])
        : "r"(a[0]), "r"(a[1]), "r"(a[2]), "r"(a[3]), "r"(b0), "r"(b1));
}

// Swizzled smem byte offset: tile row r (64B rows), 16B-granule g
__device__ __forceinline__ uint32_t swz(uint32_t r, uint32_t g) {
    return r * 64u + (((g ^ ((r >> 1) & 3u)) << 4));
}

__device__ __forceinline__ __half2 split_hl(float a, float b, __half2& lo) {
    __half ha = __float2half_rn(a), hb = __float2half_rn(b);
    lo = __halves2half2(__float2half_rn(a - __half2float(ha)),
                        __float2half_rn(b - __half2float(hb)));
    return __halves2half2(ha, hb);
}

// ---------------------------------------------------------------------------
// GEMM: C[128,256] = A[128,K] @ B[256,K]^T, fp16 split-precision HMMA
// THREE=false: 2 products (AhBh + AhBl), A hi-only      (projections)
// THREE=true : 3 products (+ AlBh), A hi+lo             (logits / output)
// 256 threads, 8 warps, warp tile 64x64
// EPI: 0 = fp32 + bias, 1 = fp32, 2 = f16 hi/lo + bias
// ---------------------------------------------------------------------------
#define BK     32
#define STAGES 4
#define DSMEM_BYTES_2P (STAGES * 40960 + 1024)
#define DSMEM_BYTES_3P (STAGES * 49152 + 1024)

template<int EPI, bool THREE>
__device__ __forceinline__ void gemm_body(
    const __half* __restrict__ Ah_, const __half* __restrict__ Al_, int lda,
    const __half* __restrict__ Bh_, const __half* __restrict__ Bl_, int ldb,
    int K,
    float* __restrict__ C, int ldc,
    __half* __restrict__ Ch, __half* __restrict__ Cl,
    const float* __restrict__ bias)
{
    constexpr uint32_t OFF_AL   = 8192;
    constexpr uint32_t OFF_BH   = THREE ? 16384 : 8192;
    constexpr uint32_t OFF_BL   = OFF_BH + 16384;
    constexpr uint32_t STAGE_BY = THREE ? 49152 : 40960;

    extern __shared__ char dsm_raw[];
    const uint32_t sb = (smem_u32(dsm_raw) + 1023u) & ~1023u;

    const int tid  = threadIdx.x;
    const int wid  = tid >> 5;
    const int lane = tid & 31;
    const int warp_m = wid & 1;
    const int warp_n = wid >> 1;

    float acc[4][8][4];
#pragma unroll
    for (int i = 0; i < 4; i++)
#pragma unroll
        for (int j = 0; j < 8; j++)
#pragma unroll
            for (int q = 0; q < 4; q++) acc[i][j][q] = 0.f;

    // cp.async mapping (rows are 64B = 32 halves)
    const int rA0 = tid >> 2, gA = tid & 3;
    const uint32_t dA0 = swz(rA0, gA), dA1 = swz(rA0 + 64, gA);
    const size_t aoff0 = (size_t)rA0 * lda + gA * 8;
    const size_t aoff1 = (size_t)(rA0 + 64) * lda + gA * 8;
    uint32_t dB[4];
    size_t boff[4];
#pragma unroll
    for (int j = 0; j < 4; j++) {
        const int r = rA0 + 64 * j;
        dB[j] = swz(r, gA);
        boff[j] = (size_t)r * ldb + gA * 8;
    }

    auto load_stage = [&](int st, int kidx) {
        const int k0 = kidx * BK;
        const uint32_t sd = sb + st * STAGE_BY;
        cpa16(sd + dA0, Ah_ + aoff0 + k0);
        cpa16(sd + dA1, Ah_ + aoff1 + k0);
        if (THREE) {
            cpa16(sd + OFF_AL + dA0, Al_ + aoff0 + k0);
            cpa16(sd + OFF_AL + dA1, Al_ + aoff1 + k0);
        }
#pragma unroll
        for (int j = 0; j < 4; j++)
            cpa16(sd + OFF_BH + dB[j], Bh_ + boff[j] + k0);
#pragma unroll
        for (int j = 0; j < 4; j++)
            cpa16(sd + OFF_BL + dB[j], Bl_ + boff[j] + k0);
    };

    const int kt = K / BK;
#pragma unroll
    for (int s = 0; s < STAGES - 1; s++) {
        load_stage(s, s);
        CP_COMMIT();
    }

    const uint32_t a_row = warp_m * 64 + (lane & 7) + (((lane >> 3) & 1) << 3);
    const uint32_t a_gb  = lane >> 4;
    const uint32_t b_row = warp_n * 64 + (lane & 7) + ((lane >> 4) << 3);
    const uint32_t b_gb  = (lane >> 3) & 1;

    for (int it = 0; it < kt; it++) {
        CP_WAIT(STAGES - 2);
        __syncthreads();

        const int nf = it + STAGES - 1;
        if (nf < kt) load_stage(nf % STAGES, nf);
        CP_COMMIT();

        const uint32_t st = sb + (it % STAGES) * STAGE_BY;
#pragma unroll
        for (int ks = 0; ks < 2; ks++) {
            const uint32_t ag = ks * 2 + a_gb;
            const uint32_t bg = ks * 2 + b_gb;
            uint32_t ah[4][4], al[4][4];
#pragma unroll
            for (int mt = 0; mt < 4; mt++) {
                const uint32_t ad = st + swz(a_row + mt * 16, ag);
                LDSM4(ah[mt], ad);
                if (THREE) LDSM4(al[mt], ad + OFF_AL);
            }
            // B-chunk register double-buffer: prefetch nc+1 during nc's MMAs
            uint32_t bh[2][4], bl[2][4];
            {
                const uint32_t bd = st + swz(b_row, bg);
                LDSM4(bh[0], bd + OFF_BH);
                LDSM4(bl[0], bd + OFF_BL);
            }
#pragma unroll
            for (int nc = 0; nc < 4; nc++) {
                const int cur = nc & 1, nxt = cur ^ 1;
                if (nc < 3) {
                    const uint32_t bd = st + swz(b_row + (nc + 1) * 16, bg);
                    LDSM4(bh[nxt], bd + OFF_BH);
                    LDSM4(bl[nxt], bd + OFF_BL);
                }
#pragma unroll
                for (int mt = 0; mt < 4; mt++)
#pragma unroll
                    for (int h = 0; h < 2; h++) {
                        float* a4 = acc[mt][nc * 2 + h];
                        mma_f16(a4, ah[mt], bh[cur][h * 2], bh[cur][h * 2 + 1]);
                        mma_f16(a4, ah[mt], bl[cur][h * 2], bl[cur][h * 2 + 1]);
                        if (THREE)
                            mma_f16(a4, al[mt], bh[cur][h * 2], bh[cur][h * 2 + 1]);
                    }
            }
        }
    }

    // Epilogue
#pragma unroll
    for (int mt = 0; mt < 4; mt++) {
        const int r = warp_m * 64 + mt * 16 + (lane >> 2);
#pragma unroll
        for (int nt = 0; nt < 8; nt++) {
            const int c = warp_n * 64 + nt * 8 + (lane & 3) * 2;
            float v00 = acc[mt][nt][0], v01 = acc[mt][nt][1];
            float v10 = acc[mt][nt][2], v11 = acc[mt][nt][3];
            if (EPI == 0 || EPI == 2) {
                float2 bb = __ldg((const float2*)(bias + c));
                v00 += bb.x; v01 += bb.y; v10 += bb.x; v11 += bb.y;
            }
            if (EPI == 2) {
                __half2 l0, l1;
                __half2 h0 = split_hl(v00, v01, l0);
                __half2 h1 = split_hl(v10, v11, l1);
                *(__half2*)(Ch + (size_t)r * ldc + c) = h0;
                *(__half2*)(Ch + (size_t)(r + 8) * ldc + c) = h1;
                *(__half2*)(Cl + (size_t)r * ldc + c) = l0;
                *(__half2*)(Cl + (size_t)(r + 8) * ldc + c) = l1;
            } else {
                float2 s;
                s.x = v00; s.y = v01;
                *(float2*)(C + (size_t)r * ldc + c) = s;
                s.x = v10; s.y = v11;
                *(float2*)(C + (size_t)(r + 8) * ldc + c) = s;
            }
        }
    }
}

// Supertile remap for L2 reuse (G must divide gridDim.y)
__device__ __forceinline__ void remap_xy(int G, int& bx, int& by) {
    int lin = blockIdx.y * gridDim.x + blockIdx.x;
    int per = G * gridDim.x;
    int grp = lin / per, rem = lin % per;
    by = grp * G + (rem % G);
    bx = rem / G;
}

// ---------------------------------------------------------------------------
// GEMM kernels (CTA tile 128M x 256N)
// ---------------------------------------------------------------------------
__global__ void __launch_bounds__(256, 1)
proj_q_kernel(const float* __restrict__ bias)
{
    int bx, by; remap_xy(8, bx, by);
    const int tm = by * 128, tn = bx * 256;
    gemm_body<2, false>(g_xh + (size_t)tm * D_MODEL, nullptr, D_MODEL,
                        g_wqh + (size_t)tn * D_MODEL, g_wql + (size_t)tn * D_MODEL, D_MODEL,
                        D_MODEL, nullptr, TWO_D,
                        g_qh + (size_t)tm * TWO_D + tn, g_ql + (size_t)tm * TWO_D + tn,
                        bias + tn);
}

__global__ void __launch_bounds__(256, 1)
proj_k_kernel(const float* __restrict__ bias)
{
    int bx, by; remap_xy(8, bx, by);
    const int tm = by * 128, tn = bx * 256;
    gemm_body<2, false>(g_xh + (size_t)tm * D_MODEL, nullptr, D_MODEL,
                        g_wkh + (size_t)tn * D_MODEL, g_wkl + (size_t)tn * D_MODEL, D_MODEL,
                        D_MODEL, nullptr, TWO_D,
                        g_kh + (size_t)tm * TWO_D + tn, g_kl + (size_t)tm * TWO_D + tn,
                        bias + tn);
}

__global__ void __launch_bounds__(256, 1)
proj_v_kernel(const float* __restrict__ bias)
{
    int bx, by; remap_xy(8, bx, by);
    const int tm = by * 128, tn = bx * 256;
    gemm_body<0, false>(g_xh + (size_t)tm * D_MODEL, nullptr, D_MODEL,
                        g_wvh + (size_t)tn * D_MODEL, g_wvl + (size_t)tn * D_MODEL, D_MODEL,
                        D_MODEL, g_v + (size_t)tm * TWO_D + tn, TWO_D,
                        nullptr, nullptr, bias + tn);
}

__global__ void __launch_bounds__(256, 1)
logits_kernel()
{
    const int bz = blockIdx.z;
    const int b = bz >> 1, pair = bz & 1;
    const int tm = blockIdx.y * 128, tn = blockIdx.x * 256;
    const size_t qoff = (size_t)b * SEQ * TWO_D + (size_t)pair * D_MODEL;
    float* C = (pair ? g_l2 : g_l1) + (size_t)b * SEQ * SEQ
             + (size_t)tm * SEQ + tn;
    gemm_body<1, true>(g_qh + qoff + (size_t)tm * TWO_D,
                       g_ql + qoff + (size_t)tm * TWO_D, TWO_D,
                       g_kh + qoff + (size_t)tn * TWO_D,
                       g_kl + qoff + (size_t)tn * TWO_D, TWO_D,
                       D_MODEL, C, SEQ, nullptr, nullptr, nullptr);
}

__global__ void __launch_bounds__(256, 1)
out_gemm_kernel(float* __restrict__ out)
{
    const int b = blockIdx.z;
    int bx, by; remap_xy(4, bx, by);
    const int tm = by * 128, tn = bx * 256;
    const size_t soff = (size_t)b * SEQ * SEQ + (size_t)tm * SEQ;
    const size_t voff = (size_t)b * TWO_D * SEQ + (size_t)tn * SEQ;
    gemm_body<1, true>(g_sch + soff, g_scl + soff, SEQ,
                       g_vth + voff, g_vtl + voff, SEQ,
                       SEQ, out + (size_t)b * SEQ * TWO_D + (size_t)tm * TWO_D + tn, TWO_D,
                       nullptr, nullptr, nullptr);
}

// ---------------------------------------------------------------------------
// Support kernels
// ---------------------------------------------------------------------------
__global__ void __launch_bounds__(256)
conv_x_kernel(const float* __restrict__ src, int n4)
{
    int idx = blockIdx.x * 256 + threadIdx.x;
    if (idx >= n4) return;
    float4 v = ((const float4*)src)[idx];
    __half2* hp = (__half2*)(g_xh + (size_t)idx * 4);
    hp[0] = __halves2half2(__float2half_rn(v.x), __float2half_rn(v.y));
    hp[1] = __halves2half2(__float2half_rn(v.z), __float2half_rn(v.w));
}

__global__ void __launch_bounds__(256)
conv_w_kernel(const float* __restrict__ wq, const float* __restrict__ wk,
              const float* __restrict__ wv, int n4)
{
    int idx = blockIdx.x * 256 + threadIdx.x;
    if (idx >= n4) return;
    const int z = blockIdx.z;
    const float* src = (z == 0) ? wq : (z == 1) ? wk : wv;
    __half* h = (z == 0) ? g_wqh : (z == 1) ? g_wkh : g_wvh;
    __half* l = (z == 0) ? g_wql : (z == 1) ? g_wkl : g_wvl;
    float4 v = ((const float4*)src)[idx];
    __half2 l0, l1;
    __half2 h0 = split_hl(v.x, v.y, l0);
    __half2 h1 = split_hl(v.z, v.w, l1);
    __half2* hp = (__half2*)(h + (size_t)idx * 4);
    hp[0] = h0; hp[1] = h1;
    __half2* lp = (__half2*)(l + (size_t)idx * 4);
    lp[0] = l0; lp[1] = l1;
}

// vt[b][n][s] = v[b][s][n], split to f16 hi/lo
__global__ void __launch_bounds__(256)
transpose_v_kernel()
{
    __shared__ float t[32][33];
    const int b = blockIdx.z;
    const int s0 = blockIdx.y * 32, n0 = blockIdx.x * 32;
    const float* src = g_v + (size_t)b * SEQ * TWO_D;
    const int tx = threadIdx.x, ty = threadIdx.y;
#pragma unroll
    for (int i = ty; i < 32; i += 8)
        t[i][tx] = src[(size_t)(s0 + i) * TWO_D + n0 + tx];
    __syncthreads();
#pragma unroll
    for (int i = ty; i < 32; i += 8) {
        float v = t[tx][i];
        __half hh = __float2half_rn(v);
        size_t o = (size_t)b * TWO_D * SEQ + (size_t)(n0 + i) * SEQ + s0 + tx;
        g_vth[o] = hh;
        g_vtl[o] = __float2half_rn(v - __half2float(hh));
    }
}

// Softmax over key axis + differential combine; writes f16 hi+lo scores
__global__ void __launch_bounds__(256)
softmax_combine_kernel(const float* __restrict__ lq1, const float* __restrict__ lk1,
                       const float* __restrict__ lq2, const float* __restrict__ lk2)
{
    const int r = blockIdx.x, b = blockIdx.y;
    const size_t off = ((size_t)b * SEQ + r) * SEQ;
    const float scale = 0.04419417382415922f;  // 1/sqrt(512)
    const int tid = threadIdx.x;
    const int lane = tid & 31, warp = tid >> 5;

    float v1a = g_l1[off + tid]       * scale;
    float v1b = g_l1[off + tid + 256] * scale;
    float v2a = g_l2[off + tid]       * scale;
    float v2b = g_l2[off + tid + 256] * scale;

    __shared__ float red1[8], red2[8];

    float m1 = fmaxf(v1a, v1b), m2 = fmaxf(v2a, v2b);
#pragma unroll
    for (int o = 16; o; o >>= 1) {
        m1 = fmaxf(m1, __shfl_xor_sync(0xffffffffu, m1, o));
        m2 = fmaxf(m2, __shfl_xor_sync(0xffffffffu, m2, o));
    }
    if (lane == 0) { red1[warp] = m1; red2[warp] = m2; }
    __syncthreads();
    m1 = red1[0]; m2 = red2[0];
#pragma unroll
    for (int i = 1; i < 8; i++) { m1 = fmaxf(m1, red1[i]); m2 = fmaxf(m2, red2[i]); }
    __syncthreads();

    float e1a = expf(v1a - m1), e1b = expf(v1b - m1);
    float e2a = expf(v2a - m2), e2b = expf(v2b - m2);
    float s1 = e1a + e1b, s2 = e2a + e2b;
#pragma unroll
    for (int o = 16; o; o >>= 1) {
        s1 += __shfl_xor_sync(0xffffffffu, s1, o);
        s2 += __shfl_xor_sync(0xffffffffu, s2, o);
    }
    if (lane == 0) { red1[warp] = s1; red2[warp] = s2; }
    __syncthreads();
    s1 = 0.f; s2 = 0.f;
#pragma unroll
    for (int i = 0; i < 8; i++) { s1 += red1[i]; s2 += red2[i]; }
    const float inv1 = 1.f / s1, inv2 = 1.f / s2;

#pragma unroll
    for (int half = 0; half < 2; half++) {
        const int k = tid + half * 256;
        float e1 = half ? e1b : e1a;
        float e2 = half ? e2b : e2a;
        float lam = expf(lq1[k] * lk1[k]) - expf(lq2[k] * lk2[k]) + LAMBDA_INIT;
        float v = e1 * inv1 - lam * (e2 * inv2);
        __half hh = __float2half_rn(v);
        g_sch[off + k] = hh;
        g_scl[off + k] = __float2half_rn(v - __half2float(hh));
    }
}

// ---------------------------------------------------------------------------
extern "C" void kernel_launch(void* const* d_in, const int* in_sizes, int n_in,
                              void* d_out, int out_size)
{
    const float* x    = (const float*)d_in[0];
    const float* wq_w = (const float*)d_in[1];
    const float* wq_b = (const float*)d_in[2];
    const float* wk_w = (const float*)d_in[3];
    const float* wk_b = (const float*)d_in[4];
    const float* wv_w = (const float*)d_in[5];
    const float* wv_b = (const float*)d_in[6];
    const float* lq1  = (const float*)d_in[7];
    const float* lk1  = (const float*)d_in[8];
    const float* lq2  = (const float*)d_in[9];
    const float* lk2  = (const float*)d_in[10];
    float* out = (float*)d_out;

    cudaFuncSetAttribute(proj_q_kernel,   cudaFuncAttributeMaxDynamicSharedMemorySize, DSMEM_BYTES_2P);
    cudaFuncSetAttribute(proj_k_kernel,   cudaFuncAttributeMaxDynamicSharedMemorySize, DSMEM_BYTES_2P);
    cudaFuncSetAttribute(proj_v_kernel,   cudaFuncAttributeMaxDynamicSharedMemorySize, DSMEM_BYTES_2P);
    cudaFuncSetAttribute(logits_kernel,   cudaFuncAttributeMaxDynamicSharedMemorySize, DSMEM_BYTES_3P);
    cudaFuncSetAttribute(out_gemm_kernel, cudaFuncAttributeMaxDynamicSharedMemorySize, DSMEM_BYTES_3P);

    const int n4x = 4096 * 4096 / 4;
    const int n4w = TWO_D * 4096 / 4;

    conv_x_kernel<<<n4x / 256, 256>>>(x, n4x);                              // 0
    conv_w_kernel<<<dim3(n4w / 256, 1, 3), 256>>>(wq_w, wk_w, wv_w, n4w);   // 1

    dim3 projGrid(TWO_D / 256, (NB * SEQ) / 128);                           // (32, 32)
    proj_q_kernel<<<projGrid, 256, DSMEM_BYTES_2P>>>(wq_b);                 // 2
    proj_k_kernel<<<projGrid, 256, DSMEM_BYTES_2P>>>(wk_b);                 // 3 <- profiled
    proj_v_kernel<<<projGrid, 256, DSMEM_BYTES_2P>>>(wv_b);                 // 4

    dim3 trGrid(TWO_D / 32, SEQ / 32, NB);
    transpose_v_kernel<<<trGrid, dim3(32, 8)>>>();                          // 5

    dim3 logitsGrid(SEQ / 256, SEQ / 128, NB * 2);                          // (2, 4, 16)
    logits_kernel<<<logitsGrid, 256, DSMEM_BYTES_3P>>>();                   // 6

    dim3 smGrid(SEQ, NB);
    softmax_combine_kernel<<<smGrid, 256>>>(lq1, lk1, lq2, lk2);            // 7

    dim3 outGrid(TWO_D / 256, SEQ / 128, NB);                               // (32, 4, 8)
    out_gemm_kernel<<<outGrid, 256, DSMEM_BYTES_3P>>>(out);                 // 8
}

// round 10
// speedup vs baseline: 1.0022x; 1.0022x over previous
#include <cuda_runtime.h>
#include <cuda_fp16.h>
#include <cstdint>
#include <math.h>

// Problem constants
#define D_MODEL 4096
#define TWO_D   8192
#define NB      8
#define SEQ     512
#define LAMBDA_INIT 0.8f

// ---------------------------------------------------------------------------
// Scratch (static device globals; no runtime allocation allowed)
// ---------------------------------------------------------------------------
__device__ __align__(256) __half g_xh [(size_t)4096 * 4096];
__device__ __align__(256) __half g_wqh[(size_t)TWO_D * 4096];
__device__ __align__(256) __half g_wql[(size_t)TWO_D * 4096];
__device__ __align__(256) __half g_wkh[(size_t)TWO_D * 4096];
__device__ __align__(256) __half g_wkl[(size_t)TWO_D * 4096];
__device__ __align__(256) __half g_wvh[(size_t)TWO_D * 4096];
__device__ __align__(256) __half g_wvl[(size_t)TWO_D * 4096];
__device__ __align__(256) __half g_qh [(size_t)NB * SEQ * TWO_D];
__device__ __align__(256) __half g_ql [(size_t)NB * SEQ * TWO_D];
__device__ __align__(256) __half g_kh [(size_t)NB * SEQ * TWO_D];
__device__ __align__(256) __half g_kl [(size_t)NB * SEQ * TWO_D];
__device__ __align__(256) float  g_v  [(size_t)NB * SEQ * TWO_D];
__device__ __align__(256) __half g_vth[(size_t)NB * TWO_D * SEQ];
__device__ __align__(256) __half g_vtl[(size_t)NB * TWO_D * SEQ];
__device__ __align__(256) float  g_l1 [(size_t)NB * SEQ * SEQ];
__device__ __align__(256) float  g_l2 [(size_t)NB * SEQ * SEQ];
__device__ __align__(256) __half g_sch[(size_t)NB * SEQ * SEQ];
__device__ __align__(256) __half g_scl[(size_t)NB * SEQ * SEQ];

// ---------------------------------------------------------------------------
// PTX primitives (arch-neutral: sm_80+)
// ---------------------------------------------------------------------------
__device__ __forceinline__ uint32_t smem_u32(const void* p) {
    uint32_t a;
    asm("{ .reg .u64 t; cvta.to.shared.u64 t, %1; cvt.u32.u64 %0, t; }"
        : "=r"(a) : "l"(p));
    return a;
}

__device__ __forceinline__ void cpa16(uint32_t dst, const void* src) {
    asm volatile("cp.async.cg.shared.global [%0], [%1], 16;\n"
                 :: "r"(dst), "l"(src));
}
#define CP_COMMIT() asm volatile("cp.async.commit_group;\n" ::: "memory")
#define CP_WAIT(N)  asm volatile("cp.async.wait_group %0;\n" :: "n"(N) : "memory")

#define LDSM4(R, addr) \
    asm volatile("ldmatrix.sync.aligned.m8n8.x4.shared.b16 {%0,%1,%2,%3}, [%4];" \
        : "=r"((R)[0]), "=r"((R)[1]), "=r"((R)[2]), "=r"((R)[3]) : "r"(addr))

__device__ __forceinline__ void mma_f16(float* c, const uint32_t* a,
                                        uint32_t b0, uint32_t b1) {
    asm volatile(
        "mma.sync.aligned.m16n8k16.row.col.f32.f16.f16.f32 "
        "{%0,%1,%2,%3}, {%4,%5,%6,%7}, {%8,%9}, {%0,%1,%2,%3};"
        : "+f"(c[0]), "+f"(c[1]), "+f"(c[2]), "+f"(c[3])
        : "r"(a[0]), "r"(a[1]), "r"(a[2]), "r"(a[3]), "r"(b0), "r"(b1));
}

// Swizzled smem byte offset: tile row r (64B rows), 16B-granule g
__device__ __forceinline__ uint32_t swz(uint32_t r, uint32_t g) {
    return r * 64u + (((g ^ ((r >> 1) & 3u)) << 4));
}

__device__ __forceinline__ __half2 split_hl(float a, float b, __half2& lo) {
    __half ha = __float2half_rn(a), hb = __float2half_rn(b);
    lo = __halves2half2(__float2half_rn(a - __half2float(ha)),
                        __float2half_rn(b - __half2float(hb)));
    return __halves2half2(ha, hb);
}

// ---------------------------------------------------------------------------
// GEMM: C[128,256] = A[128,K] @ B[256,K]^T, fp16 split-precision HMMA
// THREE=false: 2 products (AhBh + AhBl), A hi-only      (projections)
// THREE=true : 3 products (+ AlBh), A hi+lo             (logits / output)
// MMAs reordered product-outermost: same-accumulator reuse distance = 8
// 256 threads, 8 warps, warp tile 64x64
// EPI: 0 = fp32 + bias, 1 = fp32, 2 = f16 hi/lo + bias
// ---------------------------------------------------------------------------
#define BK     32
#define STAGES 4
#define DSMEM_BYTES_2P (STAGES * 40960 + 1024)
#define DSMEM_BYTES_3P (STAGES * 49152 + 1024)

template<int EPI, bool THREE>
__device__ __forceinline__ void gemm_body(
    const __half* __restrict__ Ah_, const __half* __restrict__ Al_, int lda,
    const __half* __restrict__ Bh_, const __half* __restrict__ Bl_, int ldb,
    int K,
    float* __restrict__ C, int ldc,
    __half* __restrict__ Ch, __half* __restrict__ Cl,
    const float* __restrict__ bias)
{
    constexpr uint32_t OFF_AL   = 8192;
    constexpr uint32_t OFF_BH   = THREE ? 16384 : 8192;
    constexpr uint32_t OFF_BL   = OFF_BH + 16384;
    constexpr uint32_t STAGE_BY = THREE ? 49152 : 40960;

    extern __shared__ char dsm_raw[];
    const uint32_t sb = (smem_u32(dsm_raw) + 1023u) & ~1023u;

    const int tid  = threadIdx.x;
    const int wid  = tid >> 5;
    const int lane = tid & 31;
    const int warp_m = wid & 1;
    const int warp_n = wid >> 1;

    float acc[4][8][4];
#pragma unroll
    for (int i = 0; i < 4; i++)
#pragma unroll
        for (int j = 0; j < 8; j++)
#pragma unroll
            for (int q = 0; q < 4; q++) acc[i][j][q] = 0.f;

    // cp.async mapping (rows are 64B = 32 halves)
    const int rA0 = tid >> 2, gA = tid & 3;
    const uint32_t dA0 = swz(rA0, gA), dA1 = swz(rA0 + 64, gA);
    const size_t aoff0 = (size_t)rA0 * lda + gA * 8;
    const size_t aoff1 = (size_t)(rA0 + 64) * lda + gA * 8;
    uint32_t dB[4];
    size_t boff[4];
#pragma unroll
    for (int j = 0; j < 4; j++) {
        const int r = rA0 + 64 * j;
        dB[j] = swz(r, gA);
        boff[j] = (size_t)r * ldb + gA * 8;
    }

    auto load_stage = [&](int st, int kidx) {
        const int k0 = kidx * BK;
        const uint32_t sd = sb + st * STAGE_BY;
        cpa16(sd + dA0, Ah_ + aoff0 + k0);
        cpa16(sd + dA1, Ah_ + aoff1 + k0);
        if (THREE) {
            cpa16(sd + OFF_AL + dA0, Al_ + aoff0 + k0);
            cpa16(sd + OFF_AL + dA1, Al_ + aoff1 + k0);
        }
#pragma unroll
        for (int j = 0; j < 4; j++)
            cpa16(sd + OFF_BH + dB[j], Bh_ + boff[j] + k0);
#pragma unroll
        for (int j = 0; j < 4; j++)
            cpa16(sd + OFF_BL + dB[j], Bl_ + boff[j] + k0);
    };

    const int kt = K / BK;
#pragma unroll
    for (int s = 0; s < STAGES - 1; s++) {
        load_stage(s, s);
        CP_COMMIT();
    }

    const uint32_t a_row = warp_m * 64 + (lane & 7) + (((lane >> 3) & 1) << 3);
    const uint32_t a_gb  = lane >> 4;
    const uint32_t b_row = warp_n * 64 + (lane & 7) + ((lane >> 4) << 3);
    const uint32_t b_gb  = (lane >> 3) & 1;

    for (int it = 0; it < kt; it++) {
        CP_WAIT(STAGES - 2);
        __syncthreads();

        const int nf = it + STAGES - 1;
        if (nf < kt) load_stage(nf % STAGES, nf);
        CP_COMMIT();

        const uint32_t st = sb + (it % STAGES) * STAGE_BY;
#pragma unroll
        for (int ks = 0; ks < 2; ks++) {
            const uint32_t ag = ks * 2 + a_gb;
            const uint32_t bg = ks * 2 + b_gb;
            uint32_t ah[4][4], al[4][4];
#pragma unroll
            for (int mt = 0; mt < 4; mt++) {
                const uint32_t ad = st + swz(a_row + mt * 16, ag);
                LDSM4(ah[mt], ad);
                if (THREE) LDSM4(al[mt], ad + OFF_AL);
            }
            // B-chunk register double-buffer
            uint32_t bh[2][4], bl[2][4];
            {
                const uint32_t bd = st + swz(b_row, bg);
                LDSM4(bh[0], bd + OFF_BH);
                LDSM4(bl[0], bd + OFF_BL);
            }
#pragma unroll
            for (int nc = 0; nc < 4; nc++) {
                const int cur = nc & 1, nxt = cur ^ 1;
                if (nc < 3) {
                    const uint32_t bd = st + swz(b_row + (nc + 1) * 16, bg);
                    LDSM4(bh[nxt], bd + OFF_BH);
                    LDSM4(bl[nxt], bd + OFF_BL);
                }
                // Product-outermost: 8 independent accumulators per pass,
                // same-acc reuse distance = 8 MMAs (covers HMMA latency)
#pragma unroll
                for (int mt = 0; mt < 4; mt++)
#pragma unroll
                    for (int h = 0; h < 2; h++)
                        mma_f16(acc[mt][nc * 2 + h], ah[mt],
                                bh[cur][h * 2], bh[cur][h * 2 + 1]);
#pragma unroll
                for (int mt = 0; mt < 4; mt++)
#pragma unroll
                    for (int h = 0; h < 2; h++)
                        mma_f16(acc[mt][nc * 2 + h], ah[mt],
                                bl[cur][h * 2], bl[cur][h * 2 + 1]);
                if (THREE) {
#pragma unroll
                    for (int mt = 0; mt < 4; mt++)
#pragma unroll
                        for (int h = 0; h < 2; h++)
                            mma_f16(acc[mt][nc * 2 + h], al[mt],
                                    bh[cur][h * 2], bh[cur][h * 2 + 1]);
                }
            }
        }
    }

    // Epilogue
#pragma unroll
    for (int mt = 0; mt < 4; mt++) {
        const int r = warp_m * 64 + mt * 16 + (lane >> 2);
#pragma unroll
        for (int nt = 0; nt < 8; nt++) {
            const int c = warp_n * 64 + nt * 8 + (lane & 3) * 2;
            float v00 = acc[mt][nt][0], v01 = acc[mt][nt][1];
            float v10 = acc[mt][nt][2], v11 = acc[mt][nt][3];
            if (EPI == 0 || EPI == 2) {
                float2 bb = __ldg((const float2*)(bias + c));
                v00 += bb.x; v01 += bb.y; v10 += bb.x; v11 += bb.y;
            }
            if (EPI == 2) {
                __half2 l0, l1;
                __half2 h0 = split_hl(v00, v01, l0);
                __half2 h1 = split_hl(v10, v11, l1);
                *(__half2*)(Ch + (size_t)r * ldc + c) = h0;
                *(__half2*)(Ch + (size_t)(r + 8) * ldc + c) = h1;
                *(__half2*)(Cl + (size_t)r * ldc + c) = l0;
                *(__half2*)(Cl + (size_t)(r + 8) * ldc + c) = l1;
            } else {
                float2 s;
                s.x = v00; s.y = v01;
                *(float2*)(C + (size_t)r * ldc + c) = s;
                s.x = v10; s.y = v11;
                *(float2*)(C + (size_t)(r + 8) * ldc + c) = s;
            }
        }
    }
}

// Supertile remap for L2 reuse (G must divide gridDim.y)
__device__ __forceinline__ void remap_xy(int G, int& bx, int& by) {
    int lin = blockIdx.y * gridDim.x + blockIdx.x;
    int per = G * gridDim.x;
    int grp = lin / per, rem = lin % per;
    by = grp * G + (rem % G);
    bx = rem / G;
}

// ---------------------------------------------------------------------------
// GEMM kernels (CTA tile 128M x 256N)
// ---------------------------------------------------------------------------
__global__ void __launch_bounds__(256, 1)
proj_q_kernel(const float* __restrict__ bias)
{
    int bx, by; remap_xy(8, bx, by);
    const int tm = by * 128, tn = bx * 256;
    gemm_body<2, false>(g_xh + (size_t)tm * D_MODEL, nullptr, D_MODEL,
                        g_wqh + (size_t)tn * D_MODEL, g_wql + (size_t)tn * D_MODEL, D_MODEL,
                        D_MODEL, nullptr, TWO_D,
                        g_qh + (size_t)tm * TWO_D + tn, g_ql + (size_t)tm * TWO_D + tn,
                        bias + tn);
}

__global__ void __launch_bounds__(256, 1)
proj_k_kernel(const float* __restrict__ bias)
{
    int bx, by; remap_xy(8, bx, by);
    const int tm = by * 128, tn = bx * 256;
    gemm_body<2, false>(g_xh + (size_t)tm * D_MODEL, nullptr, D_MODEL,
                        g_wkh + (size_t)tn * D_MODEL, g_wkl + (size_t)tn * D_MODEL, D_MODEL,
                        D_MODEL, nullptr, TWO_D,
                        g_kh + (size_t)tm * TWO_D + tn, g_kl + (size_t)tm * TWO_D + tn,
                        bias + tn);
}

__global__ void __launch_bounds__(256, 1)
proj_v_kernel(const float* __restrict__ bias)
{
    int bx, by; remap_xy(8, bx, by);
    const int tm = by * 128, tn = bx * 256;
    gemm_body<0, false>(g_xh + (size_t)tm * D_MODEL, nullptr, D_MODEL,
                        g_wvh + (size_t)tn * D_MODEL, g_wvl + (size_t)tn * D_MODEL, D_MODEL,
                        D_MODEL, g_v + (size_t)tm * TWO_D + tn, TWO_D,
                        nullptr, nullptr, bias + tn);
}

__global__ void __launch_bounds__(256, 1)
logits_kernel()
{
    const int bz = blockIdx.z;
    const int b = bz >> 1, pair = bz & 1;
    const int tm = blockIdx.y * 128, tn = blockIdx.x * 256;
    const size_t qoff = (size_t)b * SEQ * TWO_D + (size_t)pair * D_MODEL;
    float* C = (pair ? g_l2 : g_l1) + (size_t)b * SEQ * SEQ
             + (size_t)tm * SEQ + tn;
    gemm_body<1, true>(g_qh + qoff + (size_t)tm * TWO_D,
                       g_ql + qoff + (size_t)tm * TWO_D, TWO_D,
                       g_kh + qoff + (size_t)tn * TWO_D,
                       g_kl + qoff + (size_t)tn * TWO_D, TWO_D,
                       D_MODEL, C, SEQ, nullptr, nullptr, nullptr);
}

__global__ void __launch_bounds__(256, 1)
out_gemm_kernel(float* __restrict__ out)
{
    const int b = blockIdx.z;
    int bx, by; remap_xy(4, bx, by);
    const int tm = by * 128, tn = bx * 256;
    const size_t soff = (size_t)b * SEQ * SEQ + (size_t)tm * SEQ;
    const size_t voff = (size_t)b * TWO_D * SEQ + (size_t)tn * SEQ;
    gemm_body<1, true>(g_sch + soff, g_scl + soff, SEQ,
                       g_vth + voff, g_vtl + voff, SEQ,
                       SEQ, out + (size_t)b * SEQ * TWO_D + (size_t)tm * TWO_D + tn, TWO_D,
                       nullptr, nullptr, nullptr);
}

// ---------------------------------------------------------------------------
// Support kernels
// ---------------------------------------------------------------------------
__global__ void __launch_bounds__(256)
conv_x_kernel(const float* __restrict__ src, int n4)
{
    int idx = blockIdx.x * 256 + threadIdx.x;
    if (idx >= n4) return;
    float4 v = ((const float4*)src)[idx];
    __half2* hp = (__half2*)(g_xh + (size_t)idx * 4);
    hp[0] = __halves2half2(__float2half_rn(v.x), __float2half_rn(v.y));
    hp[1] = __halves2half2(__float2half_rn(v.z), __float2half_rn(v.w));
}

__global__ void __launch_bounds__(256)
conv_w_kernel(const float* __restrict__ wq, const float* __restrict__ wk,
              const float* __restrict__ wv, int n4)
{
    int idx = blockIdx.x * 256 + threadIdx.x;
    if (idx >= n4) return;
    const int z = blockIdx.z;
    const float* src = (z == 0) ? wq : (z == 1) ? wk : wv;
    __half* h = (z == 0) ? g_wqh : (z == 1) ? g_wkh : g_wvh;
    __half* l = (z == 0) ? g_wql : (z == 1) ? g_wkl : g_wvl;
    float4 v = ((const float4*)src)[idx];
    __half2 l0, l1;
    __half2 h0 = split_hl(v.x, v.y, l0);
    __half2 h1 = split_hl(v.z, v.w, l1);
    __half2* hp = (__half2*)(h + (size_t)idx * 4);
    hp[0] = h0; hp[1] = h1;
    __half2* lp = (__half2*)(l + (size_t)idx * 4);
    lp[0] = l0; lp[1] = l1;
}

// vt[b][n][s] = v[b][s][n], split to f16 hi/lo
__global__ void __launch_bounds__(256)
transpose_v_kernel()
{
    __shared__ float t[32][33];
    const int b = blockIdx.z;
    const int s0 = blockIdx.y * 32, n0 = blockIdx.x * 32;
    const float* src = g_v + (size_t)b * SEQ * TWO_D;
    const int tx = threadIdx.x, ty = threadIdx.y;
#pragma unroll
    for (int i = ty; i < 32; i += 8)
        t[i][tx] = src[(size_t)(s0 + i) * TWO_D + n0 + tx];
    __syncthreads();
#pragma unroll
    for (int i = ty; i < 32; i += 8) {
        float v = t[tx][i];
        __half hh = __float2half_rn(v);
        size_t o = (size_t)b * TWO_D * SEQ + (size_t)(n0 + i) * SEQ + s0 + tx;
        g_vth[o] = hh;
        g_vtl[o] = __float2half_rn(v - __half2float(hh));
    }
}

// Softmax over key axis + differential combine; writes f16 hi+lo scores
__global__ void __launch_bounds__(256)
softmax_combine_kernel(const float* __restrict__ lq1, const float* __restrict__ lk1,
                       const float* __restrict__ lq2, const float* __restrict__ lk2)
{
    const int r = blockIdx.x, b = blockIdx.y;
    const size_t off = ((size_t)b * SEQ + r) * SEQ;
    const float scale = 0.04419417382415922f;  // 1/sqrt(512)
    const int tid = threadIdx.x;
    const int lane = tid & 31, warp = tid >> 5;

    float v1a = g_l1[off + tid]       * scale;
    float v1b = g_l1[off + tid + 256] * scale;
    float v2a = g_l2[off + tid]       * scale;
    float v2b = g_l2[off + tid + 256] * scale;

    __shared__ float red1[8], red2[8];

    float m1 = fmaxf(v1a, v1b), m2 = fmaxf(v2a, v2b);
#pragma unroll
    for (int o = 16; o; o >>= 1) {
        m1 = fmaxf(m1, __shfl_xor_sync(0xffffffffu, m1, o));
        m2 = fmaxf(m2, __shfl_xor_sync(0xffffffffu, m2, o));
    }
    if (lane == 0) { red1[warp] = m1; red2[warp] = m2; }
    __syncthreads();
    m1 = red1[0]; m2 = red2[0];
#pragma unroll
    for (int i = 1; i < 8; i++) { m1 = fmaxf(m1, red1[i]); m2 = fmaxf(m2, red2[i]); }
    __syncthreads();

    float e1a = expf(v1a - m1), e1b = expf(v1b - m1);
    float e2a = expf(v2a - m2), e2b = expf(v2b - m2);
    float s1 = e1a + e1b, s2 = e2a + e2b;
#pragma unroll
    for (int o = 16; o; o >>= 1) {
        s1 += __shfl_xor_sync(0xffffffffu, s1, o);
        s2 += __shfl_xor_sync(0xffffffffu, s2, o);
    }
    if (lane == 0) { red1[warp] = s1; red2[warp] = s2; }
    __syncthreads();
    s1 = 0.f; s2 = 0.f;
#pragma unroll
    for (int i = 0; i < 8; i++) { s1 += red1[i]; s2 += red2[i]; }
    const float inv1 = 1.f / s1, inv2 = 1.f / s2;

#pragma unroll
    for (int half = 0; half < 2; half++) {
        const int k = tid + half * 256;
        float e1 = half ? e1b : e1a;
        float e2 = half ? e2b : e2a;
        float lam = expf(lq1[k] * lk1[k]) - expf(lq2[k] * lk2[k]) + LAMBDA_INIT;
        float v = e1 * inv1 - lam * (e2 * inv2);
        __half hh = __float2half_rn(v);
        g_sch[off + k] = hh;
        g_scl[off + k] = __float2half_rn(v - __half2float(hh));
    }
}

// ---------------------------------------------------------------------------
extern "C" void kernel_launch(void* const* d_in, const int* in_sizes, int n_in,
                              void* d_out, int out_size)
{
    const float* x    = (const float*)d_in[0];
    const float* wq_w = (const float*)d_in[1];
    const float* wq_b = (const float*)d_in[2];
    const float* wk_w = (const float*)d_in[3];
    const float* wk_b = (const float*)d_in[4];
    const float* wv_w = (const float*)d_in[5];
    const float* wv_b = (const float*)d_in[6];
    const float* lq1  = (const float*)d_in[7];
    const float* lk1  = (const float*)d_in[8];
    const float* lq2  = (const float*)d_in[9];
    const float* lk2  = (const float*)d_in[10];
    float* out = (float*)d_out;

    cudaFuncSetAttribute(proj_q_kernel,   cudaFuncAttributeMaxDynamicSharedMemorySize, DSMEM_BYTES_2P);
    cudaFuncSetAttribute(proj_k_kernel,   cudaFuncAttributeMaxDynamicSharedMemorySize, DSMEM_BYTES_2P);
    cudaFuncSetAttribute(proj_v_kernel,   cudaFuncAttributeMaxDynamicSharedMemorySize, DSMEM_BYTES_2P);
    cudaFuncSetAttribute(logits_kernel,   cudaFuncAttributeMaxDynamicSharedMemorySize, DSMEM_BYTES_3P);
    cudaFuncSetAttribute(out_gemm_kernel, cudaFuncAttributeMaxDynamicSharedMemorySize, DSMEM_BYTES_3P);

    const int n4x = 4096 * 4096 / 4;
    const int n4w = TWO_D * 4096 / 4;

    conv_x_kernel<<<n4x / 256, 256>>>(x, n4x);                              // 0
    conv_w_kernel<<<dim3(n4w / 256, 1, 3), 256>>>(wq_w, wk_w, wv_w, n4w);   // 1

    dim3 projGrid(TWO_D / 256, (NB * SEQ) / 128);                           // (32, 32)
    proj_q_kernel<<<projGrid, 256, DSMEM_BYTES_2P>>>(wq_b);                 // 2
    proj_k_kernel<<<projGrid, 256, DSMEM_BYTES_2P>>>(wk_b);                 // 3 <- profiled
    proj_v_kernel<<<projGrid, 256, DSMEM_BYTES_2P>>>(wv_b);                 // 4

    dim3 trGrid(TWO_D / 32, SEQ / 32, NB);
    transpose_v_kernel<<<trGrid, dim3(32, 8)>>>();                          // 5

    dim3 logitsGrid(SEQ / 256, SEQ / 128, NB * 2);                          // (2, 4, 16)
    logits_kernel<<<logitsGrid, 256, DSMEM_BYTES_3P>>>();                   // 6

    dim3 smGrid(SEQ, NB);
    softmax_combine_kernel<<<smGrid, 256>>>(lq1, lk1, lq2, lk2);            // 7

    dim3 outGrid(TWO_D / 256, SEQ / 128, NB);                               // (32, 4, 8)
    out_gemm_kernel<<<outGrid, 256, DSMEM_BYTES_3P>>>(out);                 // 8
}

// round 11
// speedup vs baseline: 1.0420x; 1.0398x over previous
#include <cuda_runtime.h>
#include <cuda_fp16.h>
#include <cstdint>
#include <math.h>

// Problem constants
#define D_MODEL 4096
#define TWO_D   8192
#define NB      8
#define SEQ     512
#define LAMBDA_INIT 0.8f

// ---------------------------------------------------------------------------
// Scratch (static device globals; no runtime allocation allowed)
// ---------------------------------------------------------------------------
__device__ __align__(256) __half g_xh [(size_t)4096 * 4096];
__device__ __align__(256) __half g_wqh[(size_t)TWO_D * 4096];
__device__ __align__(256) __half g_wql[(size_t)TWO_D * 4096];
__device__ __align__(256) __half g_wkh[(size_t)TWO_D * 4096];
__device__ __align__(256) __half g_wkl[(size_t)TWO_D * 4096];
__device__ __align__(256) __half g_wvh[(size_t)TWO_D * 4096];
__device__ __align__(256) __half g_wvl[(size_t)TWO_D * 4096];
__device__ __align__(256) __half g_qh [(size_t)NB * SEQ * TWO_D];
__device__ __align__(256) __half g_ql [(size_t)NB * SEQ * TWO_D];
__device__ __align__(256) __half g_kh [(size_t)NB * SEQ * TWO_D];
__device__ __align__(256) __half g_kl [(size_t)NB * SEQ * TWO_D];
__device__ __align__(256) float  g_v  [(size_t)NB * SEQ * TWO_D];
__device__ __align__(256) __half g_vth[(size_t)NB * TWO_D * SEQ];
__device__ __align__(256) __half g_vtl[(size_t)NB * TWO_D * SEQ];
__device__ __align__(256) float  g_l1 [(size_t)NB * SEQ * SEQ];
__device__ __align__(256) float  g_l2 [(size_t)NB * SEQ * SEQ];
__device__ __align__(256) __half g_sch[(size_t)NB * SEQ * SEQ];
__device__ __align__(256) __half g_scl[(size_t)NB * SEQ * SEQ];

// ---------------------------------------------------------------------------
// PTX primitives (arch-neutral: sm_80+)
// ---------------------------------------------------------------------------
__device__ __forceinline__ uint32_t smem_u32(const void* p) {
    uint32_t a;
    asm("{ .reg .u64 t; cvta.to.shared.u64 t, %1; cvt.u32.u64 %0, t; }"
        : "=r"(a) : "l"(p));
    return a;
}

__device__ __forceinline__ void cpa16(uint32_t dst, const void* src) {
    asm volatile("cp.async.cg.shared.global [%0], [%1], 16;\n"
                 :: "r"(dst), "l"(src));
}
#define CP_COMMIT() asm volatile("cp.async.commit_group;\n" ::: "memory")
#define CP_WAIT(N)  asm volatile("cp.async.wait_group %0;\n" :: "n"(N) : "memory")

#define LDSM4(R, addr) \
    asm volatile("ldmatrix.sync.aligned.m8n8.x4.shared.b16 {%0,%1,%2,%3}, [%4];" \
        : "=r"((R)[0]), "=r"((R)[1]), "=r"((R)[2]), "=r"((R)[3]) : "r"(addr))

__device__ __forceinline__ void mma_f16(float* c, const uint32_t* a,
                                        uint32_t b0, uint32_t b1) {
    asm volatile(
        "mma.sync.aligned.m16n8k16.row.col.f32.f16.f16.f32 "
        "{%0,%1,%2,%3}, {%4,%5,%6,%7}, {%8,%9}, {%0,%1,%2,%3};"
        : "+f"(c[0]), "+f"(c[1]), "+f"(c[2]), "+f"(c[3])
        : "r"(a[0]), "r"(a[1]), "r"(a[2]), "r"(a[3]), "r"(b0), "r"(b1));
}

// Swizzled smem byte offset: tile row r (64B rows), 16B-granule g
__device__ __forceinline__ uint32_t swz(uint32_t r, uint32_t g) {
    return r * 64u + (((g ^ ((r >> 1) & 3u)) << 4));
}

__device__ __forceinline__ __half2 split_hl(float a, float b, __half2& lo) {
    __half ha = __float2half_rn(a), hb = __float2half_rn(b);
    lo = __halves2half2(__float2half_rn(a - __half2float(ha)),
                        __float2half_rn(b - __half2float(hb)));
    return __halves2half2(ha, hb);
}

// ---------------------------------------------------------------------------
// GEMM: C[128,256] = A[128,K] @ B[256,K]^T, fp16 split-precision HMMA
// THREE=false: 2 products (AhBh + AhBl), A hi-only      (projections)
// THREE=true : 3 products (+ AlBh), A hi+lo             (logits / output)
// 512 threads, 16 warps (4/SMSP), warp tile 64x32 (2 M-warps x 8 N-warps)
// EPI: 0 = fp32 + bias, 1 = fp32, 2 = f16 hi/lo + bias
// ---------------------------------------------------------------------------
#define BK      32
#define STAGES  4
#define NTHREAD 512
#define DSMEM_BYTES_2P (STAGES * 40960 + 1024)
#define DSMEM_BYTES_3P (STAGES * 49152 + 1024)

template<int EPI, bool THREE>
__device__ __forceinline__ void gemm_body(
    const __half* __restrict__ Ah_, const __half* __restrict__ Al_, int lda,
    const __half* __restrict__ Bh_, const __half* __restrict__ Bl_, int ldb,
    int K,
    float* __restrict__ C, int ldc,
    __half* __restrict__ Ch, __half* __restrict__ Cl,
    const float* __restrict__ bias)
{
    constexpr uint32_t OFF_AL   = 8192;
    constexpr uint32_t OFF_BH   = THREE ? 16384 : 8192;
    constexpr uint32_t OFF_BL   = OFF_BH + 16384;
    constexpr uint32_t STAGE_BY = THREE ? 49152 : 40960;

    extern __shared__ char dsm_raw[];
    const uint32_t sb = (smem_u32(dsm_raw) + 1023u) & ~1023u;

    const int tid  = threadIdx.x;
    const int wid  = tid >> 5;
    const int lane = tid & 31;
    const int warp_m = wid & 1;       // 2 in M (64 rows each)
    const int warp_n = wid >> 1;      // 8 in N (32 cols each)

    float acc[4][4][4];
#pragma unroll
    for (int i = 0; i < 4; i++)
#pragma unroll
        for (int j = 0; j < 4; j++)
#pragma unroll
            for (int q = 0; q < 4; q++) acc[i][j][q] = 0.f;

    // cp.async mapping (rows are 64B = 32 halves; 512 threads)
    // A tile: 128 rows * 4 granules = 512  -> 1 granule/thread
    // B tile: 256 rows * 4 granules = 1024 -> 2 granules/thread
    const int rA = tid >> 2, gA = tid & 3;
    const uint32_t dA = swz(rA, gA);
    const size_t aoff = (size_t)rA * lda + gA * 8;
    const int rB0 = rA, rB1 = rA + 128;
    const uint32_t dB0 = swz(rB0, gA), dB1 = swz(rB1, gA);
    const size_t boff0 = (size_t)rB0 * ldb + gA * 8;
    const size_t boff1 = (size_t)rB1 * ldb + gA * 8;

    auto load_stage = [&](int st, int kidx) {
        const int k0 = kidx * BK;
        const uint32_t sd = sb + st * STAGE_BY;
        cpa16(sd + dA, Ah_ + aoff + k0);
        if (THREE) cpa16(sd + OFF_AL + dA, Al_ + aoff + k0);
        cpa16(sd + OFF_BH + dB0, Bh_ + boff0 + k0);
        cpa16(sd + OFF_BH + dB1, Bh_ + boff1 + k0);
        cpa16(sd + OFF_BL + dB0, Bl_ + boff0 + k0);
        cpa16(sd + OFF_BL + dB1, Bl_ + boff1 + k0);
    };

    const int kt = K / BK;
#pragma unroll
    for (int s = 0; s < STAGES - 1; s++) {
        load_stage(s, s);
        CP_COMMIT();
    }

    const uint32_t a_row = warp_m * 64 + (lane & 7) + (((lane >> 3) & 1) << 3);
    const uint32_t a_gb  = lane >> 4;
    const uint32_t b_row = warp_n * 32 + (lane & 7) + ((lane >> 4) << 3);
    const uint32_t b_gb  = (lane >> 3) & 1;

    for (int it = 0; it < kt; it++) {
        CP_WAIT(STAGES - 2);
        __syncthreads();

        const int nf = it + STAGES - 1;
        if (nf < kt) load_stage(nf % STAGES, nf);
        CP_COMMIT();

        const uint32_t st = sb + (it % STAGES) * STAGE_BY;
#pragma unroll
        for (int ks = 0; ks < 2; ks++) {
            const uint32_t ag = ks * 2 + a_gb;
            const uint32_t bg = ks * 2 + b_gb;
            uint32_t ah[4][4], al[4][4];
#pragma unroll
            for (int mt = 0; mt < 4; mt++) {
                const uint32_t ad = st + swz(a_row + mt * 16, ag);
                LDSM4(ah[mt], ad);
                if (THREE) LDSM4(al[mt], ad + OFF_AL);
            }
            uint32_t bh[2][4], bl[2][4];
#pragma unroll
            for (int nc = 0; nc < 2; nc++) {
                const uint32_t bd = st + swz(b_row + nc * 16, bg);
                LDSM4(bh[nc], bd + OFF_BH);
                LDSM4(bl[nc], bd + OFF_BL);
            }
            // Product-outermost: 8 independent accumulators per pass
#pragma unroll
            for (int mt = 0; mt < 4; mt++)
#pragma unroll
                for (int nt = 0; nt < 4; nt++) {
                    const int nc = nt >> 1, h = nt & 1;
                    mma_f16(acc[mt][nt], ah[mt], bh[nc][h * 2], bh[nc][h * 2 + 1]);
                }
#pragma unroll
            for (int mt = 0; mt < 4; mt++)
#pragma unroll
                for (int nt = 0; nt < 4; nt++) {
                    const int nc = nt >> 1, h = nt & 1;
                    mma_f16(acc[mt][nt], ah[mt], bl[nc][h * 2], bl[nc][h * 2 + 1]);
                }
            if (THREE) {
#pragma unroll
                for (int mt = 0; mt < 4; mt++)
#pragma unroll
                    for (int nt = 0; nt < 4; nt++) {
                        const int nc = nt >> 1, h = nt & 1;
                        mma_f16(acc[mt][nt], al[mt], bh[nc][h * 2], bh[nc][h * 2 + 1]);
                    }
            }
        }
    }

    // Epilogue: warp tile 64x32
#pragma unroll
    for (int mt = 0; mt < 4; mt++) {
        const int r = warp_m * 64 + mt * 16 + (lane >> 2);
#pragma unroll
        for (int nt = 0; nt < 4; nt++) {
            const int c = warp_n * 32 + nt * 8 + (lane & 3) * 2;
            float v00 = acc[mt][nt][0], v01 = acc[mt][nt][1];
            float v10 = acc[mt][nt][2], v11 = acc[mt][nt][3];
            if (EPI == 0 || EPI == 2) {
                float2 bb = __ldg((const float2*)(bias + c));
                v00 += bb.x; v01 += bb.y; v10 += bb.x; v11 += bb.y;
            }
            if (EPI == 2) {
                __half2 l0, l1;
                __half2 h0 = split_hl(v00, v01, l0);
                __half2 h1 = split_hl(v10, v11, l1);
                *(__half2*)(Ch + (size_t)r * ldc + c) = h0;
                *(__half2*)(Ch + (size_t)(r + 8) * ldc + c) = h1;
                *(__half2*)(Cl + (size_t)r * ldc + c) = l0;
                *(__half2*)(Cl + (size_t)(r + 8) * ldc + c) = l1;
            } else {
                float2 s;
                s.x = v00; s.y = v01;
                *(float2*)(C + (size_t)r * ldc + c) = s;
                s.x = v10; s.y = v11;
                *(float2*)(C + (size_t)(r + 8) * ldc + c) = s;
            }
        }
    }
}

// Supertile remap for L2 reuse (G must divide gridDim.y)
__device__ __forceinline__ void remap_xy(int G, int& bx, int& by) {
    int lin = blockIdx.y * gridDim.x + blockIdx.x;
    int per = G * gridDim.x;
    int grp = lin / per, rem = lin % per;
    by = grp * G + (rem % G);
    bx = rem / G;
}

// ---------------------------------------------------------------------------
// GEMM kernels (CTA tile 128M x 256N, 512 threads)
// ---------------------------------------------------------------------------
__global__ void __launch_bounds__(NTHREAD, 1)
proj_q_kernel(const float* __restrict__ bias)
{
    int bx, by; remap_xy(8, bx, by);
    const int tm = by * 128, tn = bx * 256;
    gemm_body<2, false>(g_xh + (size_t)tm * D_MODEL, nullptr, D_MODEL,
                        g_wqh + (size_t)tn * D_MODEL, g_wql + (size_t)tn * D_MODEL, D_MODEL,
                        D_MODEL, nullptr, TWO_D,
                        g_qh + (size_t)tm * TWO_D + tn, g_ql + (size_t)tm * TWO_D + tn,
                        bias + tn);
}

__global__ void __launch_bounds__(NTHREAD, 1)
proj_k_kernel(const float* __restrict__ bias)
{
    int bx, by; remap_xy(8, bx, by);
    const int tm = by * 128, tn = bx * 256;
    gemm_body<2, false>(g_xh + (size_t)tm * D_MODEL, nullptr, D_MODEL,
                        g_wkh + (size_t)tn * D_MODEL, g_wkl + (size_t)tn * D_MODEL, D_MODEL,
                        D_MODEL, nullptr, TWO_D,
                        g_kh + (size_t)tm * TWO_D + tn, g_kl + (size_t)tm * TWO_D + tn,
                        bias + tn);
}

__global__ void __launch_bounds__(NTHREAD, 1)
proj_v_kernel(const float* __restrict__ bias)
{
    int bx, by; remap_xy(8, bx, by);
    const int tm = by * 128, tn = bx * 256;
    gemm_body<0, false>(g_xh + (size_t)tm * D_MODEL, nullptr, D_MODEL,
                        g_wvh + (size_t)tn * D_MODEL, g_wvl + (size_t)tn * D_MODEL, D_MODEL,
                        D_MODEL, g_v + (size_t)tm * TWO_D + tn, TWO_D,
                        nullptr, nullptr, bias + tn);
}

__global__ void __launch_bounds__(NTHREAD, 1)
logits_kernel()
{
    const int bz = blockIdx.z;
    const int b = bz >> 1, pair = bz & 1;
    const int tm = blockIdx.y * 128, tn = blockIdx.x * 256;
    const size_t qoff = (size_t)b * SEQ * TWO_D + (size_t)pair * D_MODEL;
    float* C = (pair ? g_l2 : g_l1) + (size_t)b * SEQ * SEQ
             + (size_t)tm * SEQ + tn;
    gemm_body<1, true>(g_qh + qoff + (size_t)tm * TWO_D,
                       g_ql + qoff + (size_t)tm * TWO_D, TWO_D,
                       g_kh + qoff + (size_t)tn * TWO_D,
                       g_kl + qoff + (size_t)tn * TWO_D, TWO_D,
                       D_MODEL, C, SEQ, nullptr, nullptr, nullptr);
}

__global__ void __launch_bounds__(NTHREAD, 1)
out_gemm_kernel(float* __restrict__ out)
{
    const int b = blockIdx.z;
    int bx, by; remap_xy(4, bx, by);
    const int tm = by * 128, tn = bx * 256;
    const size_t soff = (size_t)b * SEQ * SEQ + (size_t)tm * SEQ;
    const size_t voff = (size_t)b * TWO_D * SEQ + (size_t)tn * SEQ;
    gemm_body<1, true>(g_sch + soff, g_scl + soff, SEQ,
                       g_vth + voff, g_vtl + voff, SEQ,
                       SEQ, out + (size_t)b * SEQ * TWO_D + (size_t)tm * TWO_D + tn, TWO_D,
                       nullptr, nullptr, nullptr);
}

// ---------------------------------------------------------------------------
// Support kernels
// ---------------------------------------------------------------------------
__global__ void __launch_bounds__(256)
conv_x_kernel(const float* __restrict__ src, int n4)
{
    int idx = blockIdx.x * 256 + threadIdx.x;
    if (idx >= n4) return;
    float4 v = ((const float4*)src)[idx];
    __half2* hp = (__half2*)(g_xh + (size_t)idx * 4);
    hp[0] = __halves2half2(__float2half_rn(v.x), __float2half_rn(v.y));
    hp[1] = __halves2half2(__float2half_rn(v.z), __float2half_rn(v.w));
}

__global__ void __launch_bounds__(256)
conv_w_kernel(const float* __restrict__ wq, const float* __restrict__ wk,
              const float* __restrict__ wv, int n4)
{
    int idx = blockIdx.x * 256 + threadIdx.x;
    if (idx >= n4) return;
    const int z = blockIdx.z;
    const float* src = (z == 0) ? wq : (z == 1) ? wk : wv;
    __half* h = (z == 0) ? g_wqh : (z == 1) ? g_wkh : g_wvh;
    __half* l = (z == 0) ? g_wql : (z == 1) ? g_wkl : g_wvl;
    float4 v = ((const float4*)src)[idx];
    __half2 l0, l1;
    __half2 h0 = split_hl(v.x, v.y, l0);
    __half2 h1 = split_hl(v.z, v.w, l1);
    __half2* hp = (__half2*)(h + (size_t)idx * 4);
    hp[0] = h0; hp[1] = h1;
    __half2* lp = (__half2*)(l + (size_t)idx * 4);
    lp[0] = l0; lp[1] = l1;
}

// vt[b][n][s] = v[b][s][n], split to f16 hi/lo
__global__ void __launch_bounds__(256)
transpose_v_kernel()
{
    __shared__ float t[32][33];
    const int b = blockIdx.z;
    const int s0 = blockIdx.y * 32, n0 = blockIdx.x * 32;
    const float* src = g_v + (size_t)b * SEQ * TWO_D;
    const int tx = threadIdx.x, ty = threadIdx.y;
#pragma unroll
    for (int i = ty; i < 32; i += 8)
        t[i][tx] = src[(size_t)(s0 + i) * TWO_D + n0 + tx];
    __syncthreads();
#pragma unroll
    for (int i = ty; i < 32; i += 8) {
        float v = t[tx][i];
        __half hh = __float2half_rn(v);
        size_t o = (size_t)b * TWO_D * SEQ + (size_t)(n0 + i) * SEQ + s0 + tx;
        g_vth[o] = hh;
        g_vtl[o] = __float2half_rn(v - __half2float(hh));
    }
}

// Softmax over key axis + differential combine; writes f16 hi+lo scores
__global__ void __launch_bounds__(256)
softmax_combine_kernel(const float* __restrict__ lq1, const float* __restrict__ lk1,
                       const float* __restrict__ lq2, const float* __restrict__ lk2)
{
    const int r = blockIdx.x, b = blockIdx.y;
    const size_t off = ((size_t)b * SEQ + r) * SEQ;
    const float scale = 0.04419417382415922f;  // 1/sqrt(512)
    const int tid = threadIdx.x;
    const int lane = tid & 31, warp = tid >> 5;

    float v1a = g_l1[off + tid]       * scale;
    float v1b = g_l1[off + tid + 256] * scale;
    float v2a = g_l2[off + tid]       * scale;
    float v2b = g_l2[off + tid + 256] * scale;

    __shared__ float red1[8], red2[8];

    float m1 = fmaxf(v1a, v1b), m2 = fmaxf(v2a, v2b);
#pragma unroll
    for (int o = 16; o; o >>= 1) {
        m1 = fmaxf(m1, __shfl_xor_sync(0xffffffffu, m1, o));
        m2 = fmaxf(m2, __shfl_xor_sync(0xffffffffu, m2, o));
    }
    if (lane == 0) { red1[warp] = m1; red2[warp] = m2; }
    __syncthreads();
    m1 = red1[0]; m2 = red2[0];
#pragma unroll
    for (int i = 1; i < 8; i++) { m1 = fmaxf(m1, red1[i]); m2 = fmaxf(m2, red2[i]); }
    __syncthreads();

    float e1a = expf(v1a - m1), e1b = expf(v1b - m1);
    float e2a = expf(v2a - m2), e2b = expf(v2b - m2);
    float s1 = e1a + e1b, s2 = e2a + e2b;
#pragma unroll
    for (int o = 16; o; o >>= 1) {
        s1 += __shfl_xor_sync(0xffffffffu, s1, o);
        s2 += __shfl_xor_sync(0xffffffffu, s2, o);
    }
    if (lane == 0) { red1[warp] = s1; red2[warp] = s2; }
    __syncthreads();
    s1 = 0.f; s2 = 0.f;
#pragma unroll
    for (int i = 0; i < 8; i++) { s1 += red1[i]; s2 += red2[i]; }
    const float inv1 = 1.f / s1, inv2 = 1.f / s2;

#pragma unroll
    for (int half = 0; half < 2; half++) {
        const int k = tid + half * 256;
        float e1 = half ? e1b : e1a;
        float e2 = half ? e2b : e2a;
        float lam = expf(lq1[k] * lk1[k]) - expf(lq2[k] * lk2[k]) + LAMBDA_INIT;
        float v = e1 * inv1 - lam * (e2 * inv2);
        __half hh = __float2half_rn(v);
        g_sch[off + k] = hh;
        g_scl[off + k] = __float2half_rn(v - __half2float(hh));
    }
}

// ---------------------------------------------------------------------------
extern "C" void kernel_launch(void* const* d_in, const int* in_sizes, int n_in,
                              void* d_out, int out_size)
{
    const float* x    = (const float*)d_in[0];
    const float* wq_w = (const float*)d_in[1];
    const float* wq_b = (const float*)d_in[2];
    const float* wk_w = (const float*)d_in[3];
    const float* wk_b = (const float*)d_in[4];
    const float* wv_w = (const float*)d_in[5];
    const float* wv_b = (const float*)d_in[6];
    const float* lq1  = (const float*)d_in[7];
    const float* lk1  = (const float*)d_in[8];
    const float* lq2  = (const float*)d_in[9];
    const float* lk2  = (const float*)d_in[10];
    float* out = (float*)d_out;

    cudaFuncSetAttribute(proj_q_kernel,   cudaFuncAttributeMaxDynamicSharedMemorySize, DSMEM_BYTES_2P);
    cudaFuncSetAttribute(proj_k_kernel,   cudaFuncAttributeMaxDynamicSharedMemorySize, DSMEM_BYTES_2P);
    cudaFuncSetAttribute(proj_v_kernel,   cudaFuncAttributeMaxDynamicSharedMemorySize, DSMEM_BYTES_2P);
    cudaFuncSetAttribute(logits_kernel,   cudaFuncAttributeMaxDynamicSharedMemorySize, DSMEM_BYTES_3P);
    cudaFuncSetAttribute(out_gemm_kernel, cudaFuncAttributeMaxDynamicSharedMemorySize, DSMEM_BYTES_3P);

    const int n4x = 4096 * 4096 / 4;
    const int n4w = TWO_D * 4096 / 4;

    conv_x_kernel<<<n4x / 256, 256>>>(x, n4x);                              // 0
    conv_w_kernel<<<dim3(n4w / 256, 1, 3), 256>>>(wq_w, wk_w, wv_w, n4w);   // 1

    dim3 projGrid(TWO_D / 256, (NB * SEQ) / 128);                           // (32, 32)
    proj_q_kernel<<<projGrid, NTHREAD, DSMEM_BYTES_2P>>>(wq_b);             // 2
    proj_k_kernel<<<projGrid, NTHREAD, DSMEM_BYTES_2P>>>(wk_b);             // 3 <- profiled
    proj_v_kernel<<<projGrid, NTHREAD, DSMEM_BYTES_2P>>>(wv_b);             // 4

    dim3 trGrid(TWO_D / 32, SEQ / 32, NB);
    transpose_v_kernel<<<trGrid, dim3(32, 8)>>>();                          // 5

    dim3 logitsGrid(SEQ / 256, SEQ / 128, NB * 2);                          // (2, 4, 16)
    logits_kernel<<<logitsGrid, NTHREAD, DSMEM_BYTES_3P>>>();               // 6

    dim3 smGrid(SEQ, NB);
    softmax_combine_kernel<<<smGrid, 256>>>(lq1, lk1, lq2, lk2);            // 7

    dim3 outGrid(TWO_D / 256, SEQ / 128, NB);                               // (32, 4, 8)
    out_gemm_kernel<<<outGrid, NTHREAD, DSMEM_BYTES_3P>>>(out);             // 8
}

// round 12
// speedup vs baseline: 1.0812x; 1.0376x over previous
#include <cuda_runtime.h>
#include <cuda_fp16.h>
#include <cstdint>
#include <math.h>

// Problem constants
#define D_MODEL 4096
#define TWO_D   8192
#define NB      8
#define SEQ     512
#define LAMBDA_INIT 0.8f

// ---------------------------------------------------------------------------
// Scratch (static device globals; no runtime allocation allowed)
// ---------------------------------------------------------------------------
__device__ __align__(256) __half g_xh [(size_t)4096 * 4096];
__device__ __align__(256) __half g_wqh[(size_t)TWO_D * 4096];
__device__ __align__(256) __half g_wql[(size_t)TWO_D * 4096];
__device__ __align__(256) __half g_wkh[(size_t)TWO_D * 4096];
__device__ __align__(256) __half g_wkl[(size_t)TWO_D * 4096];
__device__ __align__(256) __half g_wvh[(size_t)TWO_D * 4096];
__device__ __align__(256) __half g_wvl[(size_t)TWO_D * 4096];
__device__ __align__(256) __half g_qh [(size_t)NB * SEQ * TWO_D];
__device__ __align__(256) __half g_ql [(size_t)NB * SEQ * TWO_D];
__device__ __align__(256) __half g_kh [(size_t)NB * SEQ * TWO_D];
__device__ __align__(256) __half g_kl [(size_t)NB * SEQ * TWO_D];
__device__ __align__(256) __half g_vh [(size_t)NB * SEQ * TWO_D];
__device__ __align__(256) __half g_vl [(size_t)NB * SEQ * TWO_D];
__device__ __align__(256) __half g_vth[(size_t)NB * TWO_D * SEQ];
__device__ __align__(256) __half g_vtl[(size_t)NB * TWO_D * SEQ];
__device__ __align__(256) float  g_l1 [(size_t)NB * SEQ * SEQ];
__device__ __align__(256) float  g_l2 [(size_t)NB * SEQ * SEQ];
__device__ __align__(256) __half g_sch[(size_t)NB * SEQ * SEQ];
__device__ __align__(256) __half g_scl[(size_t)NB * SEQ * SEQ];

// ---------------------------------------------------------------------------
// PTX primitives (arch-neutral: sm_80+)
// ---------------------------------------------------------------------------
__device__ __forceinline__ uint32_t smem_u32(const void* p) {
    uint32_t a;
    asm("{ .reg .u64 t; cvta.to.shared.u64 t, %1; cvt.u32.u64 %0, t; }"
        : "=r"(a) : "l"(p));
    return a;
}

__device__ __forceinline__ void cpa16(uint32_t dst, const void* src) {
    asm volatile("cp.async.cg.shared.global [%0], [%1], 16;\n"
                 :: "r"(dst), "l"(src));
}
#define CP_COMMIT() asm volatile("cp.async.commit_group;\n" ::: "memory")
#define CP_WAIT(N)  asm volatile("cp.async.wait_group %0;\n" :: "n"(N) : "memory")

#define LDSM4(R, addr) \
    asm volatile("ldmatrix.sync.aligned.m8n8.x4.shared.b16 {%0,%1,%2,%3}, [%4];" \
        : "=r"((R)[0]), "=r"((R)[1]), "=r"((R)[2]), "=r"((R)[3]) : "r"(addr))

__device__ __forceinline__ void mma_f16(float* c, const uint32_t* a,
                                        uint32_t b0, uint32_t b1) {
    asm volatile(
        "mma.sync.aligned.m16n8k16.row.col.f32.f16.f16.f32 "
        "{%0,%1,%2,%3}, {%4,%5,%6,%7}, {%8,%9}, {%0,%1,%2,%3};"
        : "+f"(c[0]), "+f"(c[1]), "+f"(c[2]), "+f"(c[3])
        : "r"(a[0]), "r"(a[1]), "r"(a[2]), "r"(a[3]), "r"(b0), "r"(b1));
}

// Swizzled smem byte offset: tile row r (64B rows), 16B-granule g
__device__ __forceinline__ uint32_t swz(uint32_t r, uint32_t g) {
    return r * 64u + (((g ^ ((r >> 1) & 3u)) << 4));
}

__device__ __forceinline__ __half2 split_hl(float a, float b, __half2& lo) {
    __half ha = __float2half_rn(a), hb = __float2half_rn(b);
    lo = __halves2half2(__float2half_rn(a - __half2float(ha)),
                        __float2half_rn(b - __half2float(hb)));
    return __halves2half2(ha, hb);
}

// ---------------------------------------------------------------------------
// GEMM: C[128,256] = A[128,K] @ B[256,K]^T, fp16 split-precision HMMA
// THREE=false: 2 products (AhBh + AhBl), A hi-only      (projections)
// THREE=true : 3 products (+ AlBh), A hi+lo             (logits / output)
// STG stages, prefetch distance 3.  BS = barrier step (1 or 2):
//   BS=2 (needs STG>=5): wait_group(1)+barrier on even iters only — slot
//   written at iter it is (it-2)%STG, last read 2 iters ago; barrier every
//   2 iters bounds skew < 2, and publishes 2 iters of cp.async data at once.
// 512 threads, 16 warps (4/SMSP), warp tile 64x32
// EPI: 0 = fp32 + bias, 1 = fp32, 2 = f16 hi/lo + bias
// ---------------------------------------------------------------------------
#define BK      32
#define NTHREAD 512
#define DSMEM_BYTES_2P (5 * 40960 + 1024)
#define DSMEM_BYTES_3P (4 * 49152 + 1024)

template<int EPI, bool THREE, int STG, int BS>
__device__ __forceinline__ void gemm_body(
    const __half* __restrict__ Ah_, const __half* __restrict__ Al_, int lda,
    const __half* __restrict__ Bh_, const __half* __restrict__ Bl_, int ldb,
    int K,
    float* __restrict__ C, int ldc,
    __half* __restrict__ Ch, __half* __restrict__ Cl,
    const float* __restrict__ bias)
{
    constexpr uint32_t OFF_AL   = 8192;
    constexpr uint32_t OFF_BH   = THREE ? 16384 : 8192;
    constexpr uint32_t OFF_BL   = OFF_BH + 16384;
    constexpr uint32_t STAGE_BY = THREE ? 49152 : 40960;

    extern __shared__ char dsm_raw[];
    const uint32_t sb = (smem_u32(dsm_raw) + 1023u) & ~1023u;

    const int tid  = threadIdx.x;
    const int wid  = tid >> 5;
    const int lane = tid & 31;
    const int warp_m = wid & 1;       // 2 in M (64 rows each)
    const int warp_n = wid >> 1;      // 8 in N (32 cols each)

    float acc[4][4][4];
#pragma unroll
    for (int i = 0; i < 4; i++)
#pragma unroll
        for (int j = 0; j < 4; j++)
#pragma unroll
            for (int q = 0; q < 4; q++) acc[i][j][q] = 0.f;

    // cp.async mapping (rows are 64B = 32 halves; 512 threads)
    const int rA = tid >> 2, gA = tid & 3;
    const uint32_t dA = swz(rA, gA);
    const size_t aoff = (size_t)rA * lda + gA * 8;
    const int rB0 = rA, rB1 = rA + 128;
    const uint32_t dB0 = swz(rB0, gA), dB1 = swz(rB1, gA);
    const size_t boff0 = (size_t)rB0 * ldb + gA * 8;
    const size_t boff1 = (size_t)rB1 * ldb + gA * 8;

    auto load_stage = [&](int st, int kidx) {
        const int k0 = kidx * BK;
        const uint32_t sd = sb + st * STAGE_BY;
        cpa16(sd + dA, Ah_ + aoff + k0);
        if (THREE) cpa16(sd + OFF_AL + dA, Al_ + aoff + k0);
        cpa16(sd + OFF_BH + dB0, Bh_ + boff0 + k0);
        cpa16(sd + OFF_BH + dB1, Bh_ + boff1 + k0);
        cpa16(sd + OFF_BL + dB0, Bl_ + boff0 + k0);
        cpa16(sd + OFF_BL + dB1, Bl_ + boff1 + k0);
    };

    const int kt = K / BK;
    // Prologue: prefetch distance 3 (slots 0..2), one commit group each
#pragma unroll
    for (int s = 0; s < 3; s++) {
        load_stage(s, s);
        CP_COMMIT();
    }

    const uint32_t a_row = warp_m * 64 + (lane & 7) + (((lane >> 3) & 1) << 3);
    const uint32_t a_gb  = lane >> 4;
    const uint32_t b_row = warp_n * 32 + (lane & 7) + ((lane >> 4) << 3);
    const uint32_t b_gb  = (lane >> 3) & 1;

    for (int it = 0; it < kt; it++) {
        if (BS == 1) {
            CP_WAIT(2);            // group 'it' complete
            __syncthreads();       // publish to all warps
        } else {
            if ((it & 1) == 0) {
                CP_WAIT(1);        // groups 'it' and 'it+1' complete
                __syncthreads();   // publish both iterations' data
            }
        }

        const int nf = it + 3;
        if (nf < kt) load_stage(nf % STG, nf);
        CP_COMMIT();

        const uint32_t st = sb + (it % STG) * STAGE_BY;
#pragma unroll
        for (int ks = 0; ks < 2; ks++) {
            const uint32_t ag = ks * 2 + a_gb;
            const uint32_t bg = ks * 2 + b_gb;
            uint32_t ah[4][4], al[4][4];
#pragma unroll
            for (int mt = 0; mt < 4; mt++) {
                const uint32_t ad = st + swz(a_row + mt * 16, ag);
                LDSM4(ah[mt], ad);
                if (THREE) LDSM4(al[mt], ad + OFF_AL);
            }
            uint32_t bh[2][4], bl[2][4];
#pragma unroll
            for (int nc = 0; nc < 2; nc++) {
                const uint32_t bd = st + swz(b_row + nc * 16, bg);
                LDSM4(bh[nc], bd + OFF_BH);
                LDSM4(bl[nc], bd + OFF_BL);
            }
#pragma unroll
            for (int mt = 0; mt < 4; mt++)
#pragma unroll
                for (int nt = 0; nt < 4; nt++) {
                    const int nc = nt >> 1, h = nt & 1;
                    mma_f16(acc[mt][nt], ah[mt], bh[nc][h * 2], bh[nc][h * 2 + 1]);
                }
#pragma unroll
            for (int mt = 0; mt < 4; mt++)
#pragma unroll
                for (int nt = 0; nt < 4; nt++) {
                    const int nc = nt >> 1, h = nt & 1;
                    mma_f16(acc[mt][nt], ah[mt], bl[nc][h * 2], bl[nc][h * 2 + 1]);
                }
            if (THREE) {
#pragma unroll
                for (int mt = 0; mt < 4; mt++)
#pragma unroll
                    for (int nt = 0; nt < 4; nt++) {
                        const int nc = nt >> 1, h = nt & 1;
                        mma_f16(acc[mt][nt], al[mt], bh[nc][h * 2], bh[nc][h * 2 + 1]);
                    }
            }
        }
    }

    // Epilogue: warp tile 64x32
#pragma unroll
    for (int mt = 0; mt < 4; mt++) {
        const int r = warp_m * 64 + mt * 16 + (lane >> 2);
#pragma unroll
        for (int nt = 0; nt < 4; nt++) {
            const int c = warp_n * 32 + nt * 8 + (lane & 3) * 2;
            float v00 = acc[mt][nt][0], v01 = acc[mt][nt][1];
            float v10 = acc[mt][nt][2], v11 = acc[mt][nt][3];
            if (EPI == 0 || EPI == 2) {
                float2 bb = __ldg((const float2*)(bias + c));
                v00 += bb.x; v01 += bb.y; v10 += bb.x; v11 += bb.y;
            }
            if (EPI == 2) {
                __half2 l0, l1;
                __half2 h0 = split_hl(v00, v01, l0);
                __half2 h1 = split_hl(v10, v11, l1);
                *(__half2*)(Ch + (size_t)r * ldc + c) = h0;
                *(__half2*)(Ch + (size_t)(r + 8) * ldc + c) = h1;
                *(__half2*)(Cl + (size_t)r * ldc + c) = l0;
                *(__half2*)(Cl + (size_t)(r + 8) * ldc + c) = l1;
            } else {
                float2 s;
                s.x = v00; s.y = v01;
                *(float2*)(C + (size_t)r * ldc + c) = s;
                s.x = v10; s.y = v11;
                *(float2*)(C + (size_t)(r + 8) * ldc + c) = s;
            }
        }
    }
}

// Supertile remap for L2 reuse (G must divide gridDim.y)
__device__ __forceinline__ void remap_xy(int G, int& bx, int& by) {
    int lin = blockIdx.y * gridDim.x + blockIdx.x;
    int per = G * gridDim.x;
    int grp = lin / per, rem = lin % per;
    by = grp * G + (rem % G);
    bx = rem / G;
}

// ---------------------------------------------------------------------------
// GEMM kernels (CTA tile 128M x 256N, 512 threads)
// Projections: STG=5, barrier every 2 iters.  Logits/out: STG=4, BS=1.
// ---------------------------------------------------------------------------
__global__ void __launch_bounds__(NTHREAD, 1)
proj_q_kernel(const float* __restrict__ bias)
{
    int bx, by; remap_xy(8, bx, by);
    const int tm = by * 128, tn = bx * 256;
    gemm_body<2, false, 5, 2>(g_xh + (size_t)tm * D_MODEL, nullptr, D_MODEL,
                              g_wqh + (size_t)tn * D_MODEL, g_wql + (size_t)tn * D_MODEL, D_MODEL,
                              D_MODEL, nullptr, TWO_D,
                              g_qh + (size_t)tm * TWO_D + tn, g_ql + (size_t)tm * TWO_D + tn,
                              bias + tn);
}

__global__ void __launch_bounds__(NTHREAD, 1)
proj_k_kernel(const float* __restrict__ bias)
{
    int bx, by; remap_xy(8, bx, by);
    const int tm = by * 128, tn = bx * 256;
    gemm_body<2, false, 5, 2>(g_xh + (size_t)tm * D_MODEL, nullptr, D_MODEL,
                              g_wkh + (size_t)tn * D_MODEL, g_wkl + (size_t)tn * D_MODEL, D_MODEL,
                              D_MODEL, nullptr, TWO_D,
                              g_kh + (size_t)tm * TWO_D + tn, g_kl + (size_t)tm * TWO_D + tn,
                              bias + tn);
}

__global__ void __launch_bounds__(NTHREAD, 1)
proj_v_kernel(const float* __restrict__ bias)
{
    int bx, by; remap_xy(8, bx, by);
    const int tm = by * 128, tn = bx * 256;
    gemm_body<2, false, 5, 2>(g_xh + (size_t)tm * D_MODEL, nullptr, D_MODEL,
                              g_wvh + (size_t)tn * D_MODEL, g_wvl + (size_t)tn * D_MODEL, D_MODEL,
                              D_MODEL, nullptr, TWO_D,
                              g_vh + (size_t)tm * TWO_D + tn, g_vl + (size_t)tm * TWO_D + tn,
                              bias + tn);
}

__global__ void __launch_bounds__(NTHREAD, 1)
logits_kernel()
{
    const int bz = blockIdx.z;
    const int b = bz >> 1, pair = bz & 1;
    const int tm = blockIdx.y * 128, tn = blockIdx.x * 256;
    const size_t qoff = (size_t)b * SEQ * TWO_D + (size_t)pair * D_MODEL;
    float* C = (pair ? g_l2 : g_l1) + (size_t)b * SEQ * SEQ
             + (size_t)tm * SEQ + tn;
    gemm_body<1, true, 4, 1>(g_qh + qoff + (size_t)tm * TWO_D,
                             g_ql + qoff + (size_t)tm * TWO_D, TWO_D,
                             g_kh + qoff + (size_t)tn * TWO_D,
                             g_kl + qoff + (size_t)tn * TWO_D, TWO_D,
                             D_MODEL, C, SEQ, nullptr, nullptr, nullptr);
}

__global__ void __launch_bounds__(NTHREAD, 1)
out_gemm_kernel(float* __restrict__ out)
{
    const int b = blockIdx.z;
    int bx, by; remap_xy(4, bx, by);
    const int tm = by * 128, tn = bx * 256;
    const size_t soff = (size_t)b * SEQ * SEQ + (size_t)tm * SEQ;
    const size_t voff = (size_t)b * TWO_D * SEQ + (size_t)tn * SEQ;
    gemm_body<1, true, 4, 1>(g_sch + soff, g_scl + soff, SEQ,
                             g_vth + voff, g_vtl + voff, SEQ,
                             SEQ, out + (size_t)b * SEQ * TWO_D + (size_t)tm * TWO_D + tn, TWO_D,
                             nullptr, nullptr, nullptr);
}

// ---------------------------------------------------------------------------
// Support kernels
// ---------------------------------------------------------------------------
// Fused conversion: z=0 -> x (hi only), z=1..3 -> wq/wk/wv (hi+lo)
__global__ void __launch_bounds__(256)
conv_all_kernel(const float* __restrict__ x,
                const float* __restrict__ wq, const float* __restrict__ wk,
                const float* __restrict__ wv, int n4x, int n4w)
{
    const int idx = blockIdx.x * 256 + threadIdx.x;
    const int z = blockIdx.z;
    if (z == 0) {
        if (idx >= n4x) return;
        float4 v = ((const float4*)x)[idx];
        __half2* hp = (__half2*)(g_xh + (size_t)idx * 4);
        hp[0] = __halves2half2(__float2half_rn(v.x), __float2half_rn(v.y));
        hp[1] = __halves2half2(__float2half_rn(v.z), __float2half_rn(v.w));
        return;
    }
    if (idx >= n4w) return;
    const float* src = (z == 1) ? wq : (z == 2) ? wk : wv;
    __half* h = (z == 1) ? g_wqh : (z == 2) ? g_wkh : g_wvh;
    __half* l = (z == 1) ? g_wql : (z == 2) ? g_wkl : g_wvl;
    float4 v = ((const float4*)src)[idx];
    __half2 l0, l1;
    __half2 h0 = split_hl(v.x, v.y, l0);
    __half2 h1 = split_hl(v.z, v.w, l1);
    __half2* hp = (__half2*)(h + (size_t)idx * 4);
    hp[0] = h0; hp[1] = h1;
    __half2* lp = (__half2*)(l + (size_t)idx * 4);
    lp[0] = l0; lp[1] = l1;
}

// vt[b][n][s] = v[b][s][n], hi and lo halves
__global__ void __launch_bounds__(256)
transpose_v_kernel()
{
    __shared__ __half th[32][34], tl[32][34];
    const int b = blockIdx.z;
    const int s0 = blockIdx.y * 32, n0 = blockIdx.x * 32;
    const size_t sbase = (size_t)b * SEQ * TWO_D;
    const int tx = threadIdx.x, ty = threadIdx.y;
#pragma unroll
    for (int i = ty; i < 32; i += 8) {
        size_t o = sbase + (size_t)(s0 + i) * TWO_D + n0 + tx;
        th[i][tx] = g_vh[o];
        tl[i][tx] = g_vl[o];
    }
    __syncthreads();
    const size_t dbase = (size_t)b * TWO_D * SEQ;
#pragma unroll
    for (int i = ty; i < 32; i += 8) {
        size_t o = dbase + (size_t)(n0 + i) * SEQ + s0 + tx;
        g_vth[o] = th[tx][i];
        g_vtl[o] = tl[tx][i];
    }
}

// Softmax over key axis + differential combine; writes f16 hi+lo scores
__global__ void __launch_bounds__(256)
softmax_combine_kernel(const float* __restrict__ lq1, const float* __restrict__ lk1,
                       const float* __restrict__ lq2, const float* __restrict__ lk2)
{
    const int r = blockIdx.x, b = blockIdx.y;
    const size_t off = ((size_t)b * SEQ + r) * SEQ;
    const float scale = 0.04419417382415922f;  // 1/sqrt(512)
    const int tid = threadIdx.x;
    const int lane = tid & 31, warp = tid >> 5;

    float v1a = g_l1[off + tid]       * scale;
    float v1b = g_l1[off + tid + 256] * scale;
    float v2a = g_l2[off + tid]       * scale;
    float v2b = g_l2[off + tid + 256] * scale;

    __shared__ float red1[8], red2[8];

    float m1 = fmaxf(v1a, v1b), m2 = fmaxf(v2a, v2b);
#pragma unroll
    for (int o = 16; o; o >>= 1) {
        m1 = fmaxf(m1, __shfl_xor_sync(0xffffffffu, m1, o));
        m2 = fmaxf(m2, __shfl_xor_sync(0xffffffffu, m2, o));
    }
    if (lane == 0) { red1[warp] = m1; red2[warp] = m2; }
    __syncthreads();
    m1 = red1[0]; m2 = red2[0];
#pragma unroll
    for (int i = 1; i < 8; i++) { m1 = fmaxf(m1, red1[i]); m2 = fmaxf(m2, red2[i]); }
    __syncthreads();

    float e1a = expf(v1a - m1), e1b = expf(v1b - m1);
    float e2a = expf(v2a - m2), e2b = expf(v2b - m2);
    float s1 = e1a + e1b, s2 = e2a + e2b;
#pragma unroll
    for (int o = 16; o; o >>= 1) {
        s1 += __shfl_xor_sync(0xffffffffu, s1, o);
        s2 += __shfl_xor_sync(0xffffffffu, s2, o);
    }
    if (lane == 0) { red1[warp] = s1; red2[warp] = s2; }
    __syncthreads();
    s1 = 0.f; s2 = 0.f;
#pragma unroll
    for (int i = 0; i < 8; i++) { s1 += red1[i]; s2 += red2[i]; }
    const float inv1 = 1.f / s1, inv2 = 1.f / s2;

#pragma unroll
    for (int half = 0; half < 2; half++) {
        const int k = tid + half * 256;
        float e1 = half ? e1b : e1a;
        float e2 = half ? e2b : e2a;
        float lam = expf(lq1[k] * lk1[k]) - expf(lq2[k] * lk2[k]) + LAMBDA_INIT;
        float v = e1 * inv1 - lam * (e2 * inv2);
        __half hh = __float2half_rn(v);
        g_sch[off + k] = hh;
        g_scl[off + k] = __float2half_rn(v - __half2float(hh));
    }
}

// ---------------------------------------------------------------------------
extern "C" void kernel_launch(void* const* d_in, const int* in_sizes, int n_in,
                              void* d_out, int out_size)
{
    const float* x    = (const float*)d_in[0];
    const float* wq_w = (const float*)d_in[1];
    const float* wq_b = (const float*)d_in[2];
    const float* wk_w = (const float*)d_in[3];
    const float* wk_b = (const float*)d_in[4];
    const float* wv_w = (const float*)d_in[5];
    const float* wv_b = (const float*)d_in[6];
    const float* lq1  = (const float*)d_in[7];
    const float* lk1  = (const float*)d_in[8];
    const float* lq2  = (const float*)d_in[9];
    const float* lk2  = (const float*)d_in[10];
    float* out = (float*)d_out;

    cudaFuncSetAttribute(proj_q_kernel,   cudaFuncAttributeMaxDynamicSharedMemorySize, DSMEM_BYTES_2P);
    cudaFuncSetAttribute(proj_k_kernel,   cudaFuncAttributeMaxDynamicSharedMemorySize, DSMEM_BYTES_2P);
    cudaFuncSetAttribute(proj_v_kernel,   cudaFuncAttributeMaxDynamicSharedMemorySize, DSMEM_BYTES_2P);
    cudaFuncSetAttribute(logits_kernel,   cudaFuncAttributeMaxDynamicSharedMemorySize, DSMEM_BYTES_3P);
    cudaFuncSetAttribute(out_gemm_kernel, cudaFuncAttributeMaxDynamicSharedMemorySize, DSMEM_BYTES_3P);

    const int n4x = 4096 * 4096 / 4;
    const int n4w = TWO_D * 4096 / 4;

    conv_all_kernel<<<dim3(n4w / 256, 1, 4), 256>>>(x, wq_w, wk_w, wv_w, n4x, n4w); // 0

    dim3 projGrid(TWO_D / 256, (NB * SEQ) / 128);                           // (32, 32)
    proj_q_kernel<<<projGrid, NTHREAD, DSMEM_BYTES_2P>>>(wq_b);             // 1
    proj_k_kernel<<<projGrid, NTHREAD, DSMEM_BYTES_2P>>>(wk_b);             // 2
    proj_v_kernel<<<projGrid, NTHREAD, DSMEM_BYTES_2P>>>(wv_b);             // 3 <- profiled

    dim3 trGrid(TWO_D / 32, SEQ / 32, NB);
    transpose_v_kernel<<<trGrid, dim3(32, 8)>>>();                          // 4

    dim3 logitsGrid(SEQ / 256, SEQ / 128, NB * 2);                          // (2, 4, 16)
    logits_kernel<<<logitsGrid, NTHREAD, DSMEM_BYTES_3P>>>();               // 5

    dim3 smGrid(SEQ, NB);
    softmax_combine_kernel<<<smGrid, 256>>>(lq1, lk1, lq2, lk2);            // 6

    dim3 outGrid(TWO_D / 256, SEQ / 128, NB);                               // (32, 4, 8)
    out_gemm_kernel<<<outGrid, NTHREAD, DSMEM_BYTES_3P>>>(out);             // 7
}